// round 8
// baseline (speedup 1.0000x reference)
#include <cuda_runtime.h>
#include <cuda_bf16.h>
#include <cstdint>

// Problem constants
#define BB 64
#define LL 512
#define TT 8
#define DD 1024
#define CC 3
#define NHOP 6
#define NPROJ 24          // [w_a, u_0..u_4, z_{c,k} c=0..2 k=0..5]

// Scratch (device globals — no allocation allowed)
__device__ float g_U[7 * DD * 4];      // levels 0..6 of [w_b, wout0..2], layout [(lvl*D+d)*4+c]
__device__ float g_Proj[NPROJ * DD];   // packed projection matrix [p][d]
__device__ float g_P[(size_t)BB * LL * NPROJ];  // per-row projected dots (incl. v_loc)

// packed f32x2 FMA (FFMA2) — only reachable via PTX
__device__ __forceinline__ unsigned long long fma2(unsigned long long a,
                                                   unsigned long long b,
                                                   unsigned long long c) {
    unsigned long long d;
    asm("fma.rn.f32x2 %0, %1, %2, %3;" : "=l"(d) : "l"(a), "l"(b), "l"(c));
    return d;
}

__device__ __forceinline__ uint32_t smem_u32(const void* p) {
    uint32_t a;
    asm("{ .reg .u64 t; cvta.to.shared.u64 t, %1; cvt.u32.u64 %0, t; }" : "=r"(a) : "l"(p));
    return a;
}
__device__ __forceinline__ void cp_async16(uint32_t dst, const void* src) {
    asm volatile("cp.async.cg.shared.global [%0], [%1], 16;" :: "r"(dst), "l"(src));
}
#define CP_COMMIT() asm volatile("cp.async.commit_group;")
#define CP_WAIT0()  asm volatile("cp.async.wait_group 0;")

// ---------------------------------------------------------------------------
// K0: level-0 vectors: col0 = w_b = w_attn[D:2D], col 1+c = W_out[:,c]
// ---------------------------------------------------------------------------
__global__ void k_init(const float* __restrict__ w_attn,
                       const float* __restrict__ W_out) {
    int d = blockIdx.x * blockDim.x + threadIdx.x;
    if (d < DD) {
        g_U[d * 4 + 0] = w_attn[DD + d];
        g_U[d * 4 + 1] = W_out[d * CC + 0];
        g_U[d * 4 + 2] = W_out[d * CC + 1];
        g_U[d * 4 + 3] = W_out[d * CC + 2];
    }
}

// ---------------------------------------------------------------------------
// K1: one chain step: level k+1 = W_lin @ level k  (4 columns at once).
// One CTA per output row, 256 threads, float4 loads, block reduce.
// ---------------------------------------------------------------------------
__global__ void __launch_bounds__(256) k_chain(const float* __restrict__ W, int k) {
    int row = blockIdx.x;
    int tid = threadIdx.x;
    int lane = tid & 31, warp = tid >> 5;

    const float4* Xv = (const float4*)(g_U + (size_t)k * DD * 4);
    const float4* Wv = (const float4*)(W + (size_t)row * DD);

    float4 w  = Wv[tid];
    float4 x0 = Xv[4 * tid + 0];
    float4 x1 = Xv[4 * tid + 1];
    float4 x2 = Xv[4 * tid + 2];
    float4 x3 = Xv[4 * tid + 3];

    float ax = w.x * x0.x + w.y * x1.x + w.z * x2.x + w.w * x3.x;
    float ay = w.x * x0.y + w.y * x1.y + w.z * x2.y + w.w * x3.y;
    float az = w.x * x0.z + w.y * x1.z + w.z * x2.z + w.w * x3.z;
    float aw = w.x * x0.w + w.y * x1.w + w.z * x2.w + w.w * x3.w;

    #pragma unroll
    for (int off = 16; off; off >>= 1) {
        ax += __shfl_xor_sync(0xffffffffu, ax, off);
        ay += __shfl_xor_sync(0xffffffffu, ay, off);
        az += __shfl_xor_sync(0xffffffffu, az, off);
        aw += __shfl_xor_sync(0xffffffffu, aw, off);
    }
    __shared__ float4 sred[8];
    if (lane == 0) sred[warp] = make_float4(ax, ay, az, aw);
    __syncthreads();
    if (tid == 0) {
        float4 s = sred[0];
        #pragma unroll
        for (int i = 1; i < 8; i++) {
            float4 t = sred[i];
            s.x += t.x; s.y += t.y; s.z += t.z; s.w += t.w;
        }
        ((float4*)(g_U + (size_t)(k + 1) * DD * 4))[row] = s;
    }
}

// ---------------------------------------------------------------------------
// K2: pack projections: p=0 -> w_a; p=1..5 -> u_{p-1}; p=6+c*6+k -> z_{c,k}
// ---------------------------------------------------------------------------
__global__ void k_build_proj(const float* __restrict__ w_attn) {
    int i = blockIdx.x * blockDim.x + threadIdx.x;   // 24*1024
    if (i >= NPROJ * DD) return;
    int p = i >> 10, d = i & (DD - 1);
    float v;
    if (p == 0)      v = w_attn[d];
    else if (p < 6)  v = g_U[((size_t)(p - 1) * DD + d) * 4 + 0];
    else {
        int c = (p - 6) / 6, k = (p - 6) % 6;
        v = g_U[((size_t)k * DD + d) * 4 + 1 + c];
    }
    g_Proj[i] = v;
}

// ---------------------------------------------------------------------------
// K3 (heavy): P[row][p] = v_loc(row) * dot(E[ctx[row]], Proj[p]), 24 projs.
// CTA = 32 rows, 256 threads = 16 dl x 4 pg(6 projs) x 4 rg(8 rows).
// K is processed in 16 chunks of 64 floats with a cp.async double-buffered
// pipeline (copy ch+1 overlaps compute ch).  Inner math is packed FFMA2.
// ---------------------------------------------------------------------------
__global__ void __launch_bounds__(256) k_heavy(const int* __restrict__ ctx_ids,
                                               const float* __restrict__ E,
                                               const int* __restrict__ ctx_len,
                                               const int* __restrict__ tgt_off) {
    __shared__ __align__(16) float sE[2][32][68];   // +4 pad
    __shared__ __align__(16) float sP[2][24][68];
    __shared__ int sid[32];

    int tid = threadIdx.x;
    int row0 = blockIdx.x * 32;
    if (tid < 32) sid[tid] = ctx_ids[row0 + tid];
    __syncthreads();

    int dl = tid & 15;          // 16 d-lanes (float4 each -> 64-float chunk)
    int pg = (tid >> 4) & 3;    // 4 proj groups of 6
    int rg = tid >> 6;          // 4 row groups of 8

    // staging indices (fixed per thread)
    int er0 = tid >> 4,           ec0 = tid & 15;          // E float4 #tid
    int er1 = (tid + 256) >> 4,   ec1 = tid & 15;          // E float4 #tid+256
    int pr0 = tid >> 4,           pc0 = tid & 15;          // Proj float4 #tid (tid<384)
    int pr1 = (tid + 256) >> 4,   pc1 = tid & 15;          // Proj float4 #tid+256 (tid<128)

    auto copy_chunk = [&](int ch, int buf) {
        // E tile: 32 rows x 16 float4 = 512 float4
        cp_async16(smem_u32(&sE[buf][er0][ec0 * 4]),
                   E + (size_t)sid[er0] * DD + ch * 64 + ec0 * 4);
        cp_async16(smem_u32(&sE[buf][er1][ec1 * 4]),
                   E + (size_t)sid[er1] * DD + ch * 64 + ec1 * 4);
        // Proj tile: 24 x 16 float4 = 384 float4
        if (tid < 384)  // always true for 256 threads; first 256 entries
            cp_async16(smem_u32(&sP[buf][pr0][pc0 * 4]),
                       g_Proj + (size_t)pr0 * DD + ch * 64 + pc0 * 4);
        if (tid < 128)
            cp_async16(smem_u32(&sP[buf][pr1][pc1 * 4]),
                       g_Proj + (size_t)pr1 * DD + ch * 64 + pc1 * 4);
    };

    unsigned long long acc[8][6];
    #pragma unroll
    for (int r = 0; r < 8; r++)
        #pragma unroll
        for (int p = 0; p < 6; p++) acc[r][p] = 0ull;

    copy_chunk(0, 0);
    CP_COMMIT();

    for (int ch = 0; ch < 16; ch++) {
        CP_WAIT0();
        __syncthreads();               // buf[ch&1] filled; prior compute done
        if (ch < 15) {
            copy_chunk(ch + 1, (ch + 1) & 1);   // overlaps with compute below
            CP_COMMIT();
        }

        const float (*se)[68] = sE[ch & 1];
        const float (*sp)[68] = sP[ch & 1];

        ulonglong2 pv[6];
        #pragma unroll
        for (int p = 0; p < 6; p++)
            pv[p] = *(const ulonglong2*)&sp[pg * 6 + p][dl * 4];

        #pragma unroll
        for (int r = 0; r < 8; r++) {
            ulonglong2 ev = *(const ulonglong2*)&se[rg * 8 + r][dl * 4];
            #pragma unroll
            for (int p = 0; p < 6; p++) {
                unsigned long long a = acc[r][p];
                a = fma2(ev.x, pv[p].x, a);
                a = fma2(ev.y, pv[p].y, a);
                acc[r][p] = a;
            }
        }
        __syncthreads();               // all reads of buf[ch&1] done
    }

    // reduce across the 16 d-lanes (xor stays inside each 16-lane half)
    #pragma unroll
    for (int off = 8; off; off >>= 1) {
        #pragma unroll
        for (int r = 0; r < 8; r++)
            #pragma unroll
            for (int p = 0; p < 6; p++) {
                unsigned long long o = __shfl_xor_sync(0xffffffffu, acc[r][p], off);
                float2 fa = *(float2*)&acc[r][p];
                float2 fo = *(float2*)&o;
                fa.x += fo.x; fa.y += fo.y;
                acc[r][p] = *(unsigned long long*)&fa;
            }
    }

    if (dl == 0) {
        int b = row0 >> 9;             // 32 | 512 -> whole CTA in one batch
        int len = ctx_len[b];
        int toff = tgt_off[b];
        #pragma unroll
        for (int r = 0; r < 8; r++) {
            int row = row0 + rg * 8 + r;
            int l = row & (LL - 1);
            float v = 0.f;
            if (l < len) v = 1.f - fabsf((float)(l - toff)) / (float)len;
            #pragma unroll
            for (int p = 0; p < 6; p++) {
                float2 f = *(float2*)&acc[r][p];
                g_P[(size_t)row * NPROJ + pg * 6 + p] = (f.x + f.y) * v;
            }
        }
    }
}

// ---------------------------------------------------------------------------
// K4 (solve): one CTA per batch. v_aspect projections, b_lin projections,
// 6-hop scalar recursion (softmax over L=512, 23 weighted sums per hop),
// emit 3 logits.
// ---------------------------------------------------------------------------
__global__ void __launch_bounds__(256) k_solve(
    const int* __restrict__ tgt_ids, const int* __restrict__ ctx_len,
    const int* __restrict__ tgt_len, const float* __restrict__ E,
    const float* __restrict__ b_attn, const float* __restrict__ b_lin,
    const float* __restrict__ b_out, float* __restrict__ out)
{
    int b = blockIdx.x, tid = threadIdx.x;
    int lane = tid & 31, warp = tid >> 5;

    __shared__ float semean[DD];
    __shared__ float sw[8][33];
    __shared__ float sq[6][23];   // sq[j][r]: attn_j . Proj[1+r]
    __shared__ float sbd[24];     // b_lin . Proj[p], p=1..23
    __shared__ float sc0[9];      // vec0.u_0..u_5 (0..5), vec0.z_{c,6} (6..8)
    __shared__ float sbcast[2];

    int len  = ctx_len[b];
    int tlen = tgt_len[b];

    // v_aspect (mean of target embeddings)
    for (int d = tid; d < DD; d += 256) {
        float s = 0.f;
        for (int t = 0; t < tlen; t++)
            s += E[(size_t)tgt_ids[b * TT + t] * DD + d];
        semean[d] = s / (float)tlen;
    }
    __syncthreads();

    // 32 dot products: 6 (vec0.u_h) + 3 (vec0.z_{c,6}) + 23 (b_lin.Proj_p)
    float part[32];
    #pragma unroll
    for (int i = 0; i < 32; i++) part[i] = 0.f;
    for (int d = tid; d < DD; d += 256) {
        float em = semean[d];
        float bl = b_lin[d];
        #pragma unroll
        for (int h = 0; h < 6; h++) part[h] += em * g_U[((size_t)h * DD + d) * 4 + 0];
        #pragma unroll
        for (int c = 0; c < 3; c++) part[6 + c] += em * g_U[((size_t)6 * DD + d) * 4 + 1 + c];
        #pragma unroll
        for (int p = 1; p < 24; p++) part[8 + p] += bl * g_Proj[(size_t)p * DD + d];
    }
    #pragma unroll
    for (int off = 16; off; off >>= 1)
        #pragma unroll
        for (int i = 0; i < 32; i++)
            part[i] += __shfl_xor_sync(0xffffffffu, part[i], off);
    if (lane == 0) {
        #pragma unroll
        for (int i = 0; i < 32; i++) sw[warp][i] = part[i];
    }
    __syncthreads();
    if (tid < 32) {
        float s = 0.f;
        #pragma unroll
        for (int w = 0; w < 8; w++) s += sw[w][tid];
        if (tid < 9) sc0[tid] = s;
        else         sbd[tid - 8] = s;     // tid 9..31 -> sbd[1..23]
    }
    __syncthreads();

    // pull this thread's 2 rows of P into registers
    int l0 = tid, l1 = tid + 256;
    float P0[24], P1[24];
    {
        const float4* p0 = (const float4*)(g_P + ((size_t)b * LL + l0) * NPROJ);
        const float4* p1 = (const float4*)(g_P + ((size_t)b * LL + l1) * NPROJ);
        #pragma unroll
        for (int i = 0; i < 6; i++) { ((float4*)P0)[i] = p0[i]; ((float4*)P1)[i] = p1[i]; }
    }
    float ba = b_attn[0];
    bool v0 = l0 < len, v1 = l1 < len;

    for (int j = 0; j < NHOP; j++) {
        float t = sc0[j] + ba;
        #pragma unroll
        for (int i = 0; i < 5; i++)
            if (i < j) { int k = j - 1 - i; t += sq[i][k] + sbd[1 + k]; }

        float s0 = v0 ? tanhf(P0[0] + t) : -1e30f;
        float s1 = v1 ? tanhf(P1[0] + t) : -1e30f;

        // block max
        float m = fmaxf(s0, s1);
        #pragma unroll
        for (int off = 16; off; off >>= 1) m = fmaxf(m, __shfl_xor_sync(0xffffffffu, m, off));
        if (lane == 0) sw[warp][0] = m;
        __syncthreads();
        if (tid == 0) {
            float mm = sw[0][0];
            for (int w = 1; w < 8; w++) mm = fmaxf(mm, sw[w][0]);
            sbcast[0] = mm;
        }
        __syncthreads();
        float M = sbcast[0];

        float e0 = v0 ? expf(s0 - M) : 0.f;
        float e1 = v1 ? expf(s1 - M) : 0.f;
        float zs = e0 + e1;
        #pragma unroll
        for (int off = 16; off; off >>= 1) zs += __shfl_xor_sync(0xffffffffu, zs, off);
        if (lane == 0) sw[warp][1] = zs;
        __syncthreads();
        if (tid == 0) {
            float Z = 0.f;
            for (int w = 0; w < 8; w++) Z += sw[w][1];
            sbcast[1] = 1.f / Z;
        }
        __syncthreads();
        float rz = sbcast[1];
        float a0 = e0 * rz, a1 = e1 * rz;

        // 23 weighted sums over L
        float wp[23];
        #pragma unroll
        for (int r = 0; r < 23; r++) wp[r] = a0 * P0[1 + r] + a1 * P1[1 + r];
        #pragma unroll
        for (int off = 16; off; off >>= 1)
            #pragma unroll
            for (int r = 0; r < 23; r++)
                wp[r] += __shfl_xor_sync(0xffffffffu, wp[r], off);
        if (lane == 0) {
            #pragma unroll
            for (int r = 0; r < 23; r++) sw[warp][r] = wp[r];
        }
        __syncthreads();
        if (tid < 23) {
            float s = 0.f;
            #pragma unroll
            for (int w = 0; w < 8; w++) s += sw[w][tid];
            sq[j][tid] = s;
        }
        __syncthreads();
    }

    // logits_c = vec0.z_{c,6} + sum_j (attn_j + b_lin).z_{c,5-j} + b_out_c
    if (tid < CC) {
        int c = tid;
        float lg = sc0[6 + c] + b_out[c];
        #pragma unroll
        for (int j = 0; j < NHOP; j++) {
            int k = 5 - j;
            lg += sq[j][5 + c * 6 + k] + sbd[6 + c * 6 + k];
        }
        out[b * CC + c] = lg;
    }
}

// ---------------------------------------------------------------------------
extern "C" void kernel_launch(void* const* d_in, const int* in_sizes, int n_in,
                              void* d_out, int out_size) {
    const int*   ctx_ids = (const int*)  d_in[0];
    const int*   tgt_ids = (const int*)  d_in[1];
    const int*   ctx_len = (const int*)  d_in[2];
    const int*   tgt_len = (const int*)  d_in[3];
    const int*   tgt_off = (const int*)  d_in[4];
    const float* E       = (const float*)d_in[5];
    const float* W_lin   = (const float*)d_in[6];
    const float* b_lin   = (const float*)d_in[7];
    const float* w_attn  = (const float*)d_in[8];
    const float* b_attn  = (const float*)d_in[9];
    const float* W_out   = (const float*)d_in[10];
    const float* b_out   = (const float*)d_in[11];
    float* out = (float*)d_out;

    k_init<<<4, 256>>>(w_attn, W_out);
    for (int k = 0; k < NHOP; k++)
        k_chain<<<DD, 256>>>(W_lin, k);
    k_build_proj<<<96, 256>>>(w_attn);
    k_heavy<<<(BB * LL) / 32, 256>>>(ctx_ids, E, ctx_len, tgt_off);
    k_solve<<<BB, 256>>>(tgt_ids, ctx_len, tgt_len, E, b_attn, b_lin, b_out, out);
}

// round 13
// speedup vs baseline: 1.4002x; 1.4002x over previous
#include <cuda_runtime.h>
#include <cuda_bf16.h>
#include <cstdint>

// Problem constants
#define BB 64
#define LL 512
#define TT 8
#define DD 1024
#define CC 3
#define NHOP 6
#define NPROJ 24          // [w_a, u_0..u_4, z_{c,k} c=0..2 k=0..5]
#define CHAIN_CTAS 128
#define HEAVY_CTAS 148
#define NBLK ((BB * LL) / 32)   // 1024 row-blocks of 32

// Scratch (device globals — no allocation allowed)
__device__ float g_U[7 * DD * 4];      // levels 0..6 of [w_b, wout0..2], layout [(lvl*D+d)*4+c]
__device__ float g_Proj[NPROJ * DD];   // packed projection matrix [p][d]
__device__ float g_P[(size_t)BB * LL * NPROJ];  // per-row projected dots (incl. v_loc)

// software grid barrier state (persistent across replays; gen monotonic)
__device__ unsigned g_cnt = 0;
__device__ unsigned g_gen = 0;

// packed f32x2 FMA (FFMA2) — only reachable via PTX
__device__ __forceinline__ unsigned long long fma2(unsigned long long a,
                                                   unsigned long long b,
                                                   unsigned long long c) {
    unsigned long long d;
    asm("fma.rn.f32x2 %0, %1, %2, %3;" : "=l"(d) : "l"(a), "l"(b), "l"(c));
    return d;
}

__device__ __forceinline__ void grid_sync() {
    __threadfence();
    __syncthreads();
    if (threadIdx.x == 0) {
        // read gen BEFORE arriving (release cannot happen until all arrive)
        unsigned gen = *(volatile unsigned*)&g_gen;
        unsigned t = atomicAdd(&g_cnt, 1);
        if (t == CHAIN_CTAS - 1) {
            g_cnt = 0;
            __threadfence();
            atomicAdd(&g_gen, 1);
        } else {
            while (*(volatile unsigned*)&g_gen == gen) { }
        }
    }
    __syncthreads();
}

// ---------------------------------------------------------------------------
// K1 (fused chain): init level-0, 6x (level k+1 = W_lin @ level k, 4 cols),
// then pack the 24 projection vectors. ONE launch, 128 all-resident CTAs with
// a software grid barrier between steps. X kept in smem as SoA (conflict-free).
// ---------------------------------------------------------------------------
__global__ void __launch_bounds__(256) k_chain_all(
    const float* __restrict__ W, const float* __restrict__ w_attn,
    const float* __restrict__ W_out)
{
    __shared__ float sx0[DD], sx1[DD], sx2[DD], sx3[DD];
    int tid = threadIdx.x, bid = blockIdx.x;
    int lane = tid & 31, warp = tid >> 5;
    int gt = bid * 256 + tid;              // 0 .. 32767

    // init level 0: col0 = w_b, col 1+c = W_out[:,c]
    for (int d = gt; d < DD; d += CHAIN_CTAS * 256) {
        g_U[d * 4 + 0] = w_attn[DD + d];
        g_U[d * 4 + 1] = W_out[d * CC + 0];
        g_U[d * 4 + 2] = W_out[d * CC + 1];
        g_U[d * 4 + 3] = W_out[d * CC + 2];
    }
    grid_sync();

    for (int k = 0; k < NHOP; k++) {
        // load X level k into smem SoA (L2-only loads: avoid stale L1)
        const float4* Xv = (const float4*)(g_U + (size_t)k * DD * 4);
        for (int i = tid; i < DD; i += 256) {
            float4 v = __ldcg(Xv + i);
            sx0[i] = v.x; sx1[i] = v.y; sx2[i] = v.z; sx3[i] = v.w;
        }
        __syncthreads();

        // 8 rows per CTA, one per warp
        int row = bid * 8 + warp;
        const float4* Wv = (const float4*)(W + (size_t)row * DD);
        float a0 = 0.f, a1 = 0.f, a2 = 0.f, a3 = 0.f;
        #pragma unroll
        for (int pass = 0; pass < 8; pass++) {
            int idx = pass * 32 + lane;      // float4 index into W row
            float4 w = Wv[idx];
            float4 x0 = *(const float4*)&sx0[idx * 4];
            float4 x1 = *(const float4*)&sx1[idx * 4];
            float4 x2 = *(const float4*)&sx2[idx * 4];
            float4 x3 = *(const float4*)&sx3[idx * 4];
            a0 += w.x * x0.x + w.y * x0.y + w.z * x0.z + w.w * x0.w;
            a1 += w.x * x1.x + w.y * x1.y + w.z * x1.z + w.w * x1.w;
            a2 += w.x * x2.x + w.y * x2.y + w.z * x2.z + w.w * x2.w;
            a3 += w.x * x3.x + w.y * x3.y + w.z * x3.z + w.w * x3.w;
        }
        #pragma unroll
        for (int off = 16; off; off >>= 1) {
            a0 += __shfl_xor_sync(0xffffffffu, a0, off);
            a1 += __shfl_xor_sync(0xffffffffu, a1, off);
            a2 += __shfl_xor_sync(0xffffffffu, a2, off);
            a3 += __shfl_xor_sync(0xffffffffu, a3, off);
        }
        if (lane == 0)
            ((float4*)(g_U + (size_t)(k + 1) * DD * 4))[row] = make_float4(a0, a1, a2, a3);

        grid_sync();     // level k+1 complete & visible
    }

    // pack projections: p=0 -> w_a; p=1..5 -> u_{p-1}; p=6+c*6+kk -> z_{c,kk}
    for (int i = gt; i < NPROJ * DD; i += CHAIN_CTAS * 256) {
        int p = i >> 10, d = i & (DD - 1);
        float v;
        if (p == 0)      v = w_attn[d];
        else if (p < 6)  v = __ldcg(&g_U[((size_t)(p - 1) * DD + d) * 4 + 0]);
        else {
            int c = (p - 6) / 6, kk = (p - 6) % 6;
            v = __ldcg(&g_U[((size_t)kk * DD + d) * 4 + 1 + c]);
        }
        g_Proj[i] = v;
    }
}

// ---------------------------------------------------------------------------
// K3 (heavy): P[row][p] = v_loc(row) * dot(E[ctx[row]], Proj[p]), 24 projs.
// Persistent grid=148.  Proj (96 KB) loaded into dynamic smem ONCE per CTA.
// E read straight to registers (coalesced LDG.128, register double-buffer);
// NO barriers in the main loop.  Thread tile: 8 rows x 6 projs, FFMA2.
// Thread map: dl = tid&15 (d-slice), pg = (tid>>4)&3 (6 projs), rg = tid>>6 (8 rows).
// ---------------------------------------------------------------------------
__global__ void __launch_bounds__(256, 1) k_heavy(
    const int* __restrict__ ctx_ids, const float* __restrict__ E,
    const int* __restrict__ ctx_len, const int* __restrict__ tgt_off)
{
    extern __shared__ float sproj[];   // [24][1024] = 96 KB
    int tid = threadIdx.x;

    {   // one-time Proj load
        const float4* src = (const float4*)g_Proj;
        float4* dst = (float4*)sproj;
        for (int i = tid; i < NPROJ * DD / 4; i += 256) dst[i] = src[i];
    }
    __syncthreads();

    int dl = tid & 15;
    int pg = (tid >> 4) & 3;
    int rg = tid >> 6;
    const float* pbase = sproj + (size_t)(pg * 6) * DD + dl * 4;

    for (int blk = blockIdx.x; blk < NBLK; blk += HEAVY_CTAS) {
        int row0 = blk * 32;

        const float4* pr[8];
        #pragma unroll
        for (int r = 0; r < 8; r++) {
            int sidr = __ldg(&ctx_ids[row0 + rg * 8 + r]);
            pr[r] = (const float4*)(E + (size_t)sidr * DD) + dl;
        }

        unsigned long long acc[8][6];
        #pragma unroll
        for (int r = 0; r < 8; r++)
            #pragma unroll
            for (int p = 0; p < 6; p++) acc[r][p] = 0ull;

        float4 evA[8];
        #pragma unroll
        for (int r = 0; r < 8; r++) evA[r] = __ldg(&pr[r][0]);

        #pragma unroll 2
        for (int ch = 0; ch < 16; ch++) {
            float4 evB[8];
            if (ch < 15) {
                #pragma unroll
                for (int r = 0; r < 8; r++) evB[r] = __ldg(&pr[r][(ch + 1) * 16]);
            }
            ulonglong2 pv[6];
            #pragma unroll
            for (int p = 0; p < 6; p++)
                pv[p] = *(const ulonglong2*)(pbase + (size_t)p * DD + ch * 64);

            #pragma unroll
            for (int r = 0; r < 8; r++) {
                ulonglong2 e2 = *(ulonglong2*)&evA[r];
                #pragma unroll
                for (int p = 0; p < 6; p++) {
                    unsigned long long a = acc[r][p];
                    a = fma2(e2.x, pv[p].x, a);
                    a = fma2(e2.y, pv[p].y, a);
                    acc[r][p] = a;
                }
            }
            #pragma unroll
            for (int r = 0; r < 8; r++) evA[r] = evB[r];
        }

        // collapse packed halves, then reduce over the 16 d-lanes
        float s[8][6];
        #pragma unroll
        for (int r = 0; r < 8; r++)
            #pragma unroll
            for (int p = 0; p < 6; p++) {
                float2 f = *(float2*)&acc[r][p];
                s[r][p] = f.x + f.y;
            }
        #pragma unroll
        for (int off = 8; off; off >>= 1)
            #pragma unroll
            for (int r = 0; r < 8; r++)
                #pragma unroll
                for (int p = 0; p < 6; p++)
                    s[r][p] += __shfl_xor_sync(0xffffffffu, s[r][p], off);

        if (dl == 0) {
            int b = row0 >> 9;
            int len = __ldg(&ctx_len[b]);
            int toff = __ldg(&tgt_off[b]);
            #pragma unroll
            for (int r = 0; r < 8; r++) {
                int row = row0 + rg * 8 + r;
                int l = row & (LL - 1);
                float v = 0.f;
                if (l < len) v = 1.f - fabsf((float)(l - toff)) / (float)len;
                float2* dst = (float2*)(g_P + (size_t)row * NPROJ + pg * 6);
                dst[0] = make_float2(s[r][0] * v, s[r][1] * v);
                dst[1] = make_float2(s[r][2] * v, s[r][3] * v);
                dst[2] = make_float2(s[r][4] * v, s[r][5] * v);
            }
        }
    }
}

// ---------------------------------------------------------------------------
// K4 (solve): one CTA per batch. v_aspect projections, b_lin projections,
// 6-hop scalar recursion (softmax over L=512, 23 weighted sums per hop),
// emit 3 logits.
// ---------------------------------------------------------------------------
__global__ void __launch_bounds__(256) k_solve(
    const int* __restrict__ tgt_ids, const int* __restrict__ ctx_len,
    const int* __restrict__ tgt_len, const float* __restrict__ E,
    const float* __restrict__ b_attn, const float* __restrict__ b_lin,
    const float* __restrict__ b_out, float* __restrict__ out)
{
    int b = blockIdx.x, tid = threadIdx.x;
    int lane = tid & 31, warp = tid >> 5;

    __shared__ float semean[DD];
    __shared__ float sw[8][33];
    __shared__ float sq[6][23];   // sq[j][r]: attn_j . Proj[1+r]
    __shared__ float sbd[24];     // b_lin . Proj[p], p=1..23
    __shared__ float sc0[9];      // vec0.u_0..u_5 (0..5), vec0.z_{c,6} (6..8)
    __shared__ float sbcast[2];

    int len  = ctx_len[b];
    int tlen = tgt_len[b];

    // v_aspect (mean of target embeddings)
    for (int d = tid; d < DD; d += 256) {
        float s = 0.f;
        for (int t = 0; t < tlen; t++)
            s += E[(size_t)tgt_ids[b * TT + t] * DD + d];
        semean[d] = s / (float)tlen;
    }
    __syncthreads();

    // 32 dot products: 6 (vec0.u_h) + 3 (vec0.z_{c,6}) + 23 (b_lin.Proj_p)
    float part[32];
    #pragma unroll
    for (int i = 0; i < 32; i++) part[i] = 0.f;
    for (int d = tid; d < DD; d += 256) {
        float em = semean[d];
        float bl = b_lin[d];
        #pragma unroll
        for (int h = 0; h < 6; h++) part[h] += em * g_U[((size_t)h * DD + d) * 4 + 0];
        #pragma unroll
        for (int c = 0; c < 3; c++) part[6 + c] += em * g_U[((size_t)6 * DD + d) * 4 + 1 + c];
        #pragma unroll
        for (int p = 1; p < 24; p++) part[8 + p] += bl * g_Proj[(size_t)p * DD + d];
    }
    #pragma unroll
    for (int off = 16; off; off >>= 1)
        #pragma unroll
        for (int i = 0; i < 32; i++)
            part[i] += __shfl_xor_sync(0xffffffffu, part[i], off);
    if (lane == 0) {
        #pragma unroll
        for (int i = 0; i < 32; i++) sw[warp][i] = part[i];
    }
    __syncthreads();
    if (tid < 32) {
        float s = 0.f;
        #pragma unroll
        for (int w = 0; w < 8; w++) s += sw[w][tid];
        if (tid < 9) sc0[tid] = s;
        else         sbd[tid - 8] = s;     // tid 9..31 -> sbd[1..23]
    }
    __syncthreads();

    // pull this thread's 2 rows of P into registers
    int l0 = tid, l1 = tid + 256;
    float P0[24], P1[24];
    {
        const float4* p0 = (const float4*)(g_P + ((size_t)b * LL + l0) * NPROJ);
        const float4* p1 = (const float4*)(g_P + ((size_t)b * LL + l1) * NPROJ);
        #pragma unroll
        for (int i = 0; i < 6; i++) { ((float4*)P0)[i] = p0[i]; ((float4*)P1)[i] = p1[i]; }
    }
    float ba = b_attn[0];
    bool v0 = l0 < len, v1 = l1 < len;

    for (int j = 0; j < NHOP; j++) {
        float t = sc0[j] + ba;
        #pragma unroll
        for (int i = 0; i < 5; i++)
            if (i < j) { int k = j - 1 - i; t += sq[i][k] + sbd[1 + k]; }

        float s0 = v0 ? tanhf(P0[0] + t) : -1e30f;
        float s1 = v1 ? tanhf(P1[0] + t) : -1e30f;

        // block max
        float m = fmaxf(s0, s1);
        #pragma unroll
        for (int off = 16; off; off >>= 1) m = fmaxf(m, __shfl_xor_sync(0xffffffffu, m, off));
        if (lane == 0) sw[warp][0] = m;
        __syncthreads();
        if (tid == 0) {
            float mm = sw[0][0];
            for (int w = 1; w < 8; w++) mm = fmaxf(mm, sw[w][0]);
            sbcast[0] = mm;
        }
        __syncthreads();
        float M = sbcast[0];

        float e0 = v0 ? expf(s0 - M) : 0.f;
        float e1 = v1 ? expf(s1 - M) : 0.f;
        float zs = e0 + e1;
        #pragma unroll
        for (int off = 16; off; off >>= 1) zs += __shfl_xor_sync(0xffffffffu, zs, off);
        if (lane == 0) sw[warp][1] = zs;
        __syncthreads();
        if (tid == 0) {
            float Z = 0.f;
            for (int w = 0; w < 8; w++) Z += sw[w][1];
            sbcast[1] = 1.f / Z;
        }
        __syncthreads();
        float rz = sbcast[1];
        float a0 = e0 * rz, a1 = e1 * rz;

        // 23 weighted sums over L
        float wp[23];
        #pragma unroll
        for (int r = 0; r < 23; r++) wp[r] = a0 * P0[1 + r] + a1 * P1[1 + r];
        #pragma unroll
        for (int off = 16; off; off >>= 1)
            #pragma unroll
            for (int r = 0; r < 23; r++)
                wp[r] += __shfl_xor_sync(0xffffffffu, wp[r], off);
        if (lane == 0) {
            #pragma unroll
            for (int r = 0; r < 23; r++) sw[warp][r] = wp[r];
        }
        __syncthreads();
        if (tid < 23) {
            float s = 0.f;
            #pragma unroll
            for (int w = 0; w < 8; w++) s += sw[w][tid];
            sq[j][tid] = s;
        }
        __syncthreads();
    }

    // logits_c = vec0.z_{c,6} + sum_j (attn_j + b_lin).z_{c,5-j} + b_out_c
    if (tid < CC) {
        int c = tid;
        float lg = sc0[6 + c] + b_out[c];
        #pragma unroll
        for (int j = 0; j < NHOP; j++) {
            int k = 5 - j;
            lg += sq[j][5 + c * 6 + k] + sbd[6 + c * 6 + k];
        }
        out[b * CC + c] = lg;
    }
}

// ---------------------------------------------------------------------------
extern "C" void kernel_launch(void* const* d_in, const int* in_sizes, int n_in,
                              void* d_out, int out_size) {
    const int*   ctx_ids = (const int*)  d_in[0];
    const int*   tgt_ids = (const int*)  d_in[1];
    const int*   ctx_len = (const int*)  d_in[2];
    const int*   tgt_len = (const int*)  d_in[3];
    const int*   tgt_off = (const int*)  d_in[4];
    const float* E       = (const float*)d_in[5];
    const float* W_lin   = (const float*)d_in[6];
    const float* b_lin   = (const float*)d_in[7];
    const float* w_attn  = (const float*)d_in[8];
    const float* b_attn  = (const float*)d_in[9];
    const float* W_out   = (const float*)d_in[10];
    const float* b_out   = (const float*)d_in[11];
    float* out = (float*)d_out;

    cudaFuncSetAttribute(k_heavy, cudaFuncAttributeMaxDynamicSharedMemorySize,
                         NPROJ * DD * (int)sizeof(float));

    k_chain_all<<<CHAIN_CTAS, 256>>>(W_lin, w_attn, W_out);
    k_heavy<<<HEAVY_CTAS, 256, NPROJ * DD * sizeof(float)>>>(ctx_ids, E, ctx_len, tgt_off);
    k_solve<<<BB, 256>>>(tgt_ids, ctx_len, tgt_len, E, b_attn, b_lin, b_out, out);
}